// round 15
// baseline (speedup 1.0000x reference)
#include <cuda_runtime.h>

// DeepSeek-V3 grouped top-k router, round 14.
// Half-warp token ownership: lanes 0-15 own token A (16 experts/lane),
// lanes 16-31 own token B. Group merge = 1 shfl level; one ballot.
// Champion sort/extraction (u64 keys, butterfly+ballot) untouched.
// All tie-breaks bit-exact vs jax.lax.top_k.

#define FULL  0xFFFFFFFFu
#define TOPK  8
#define SCALE 2.5f

__device__ __forceinline__ unsigned f2ord(float f) {
    unsigned u = __float_as_uint(f);
    return u ^ (unsigned)(((int)u >> 31) | 0x80000000);   // monotonic f32->u32
}

// descending compare-exchange on u64 keys
#define CE(i, j)                                              \
    {                                                         \
        unsigned long long _a = k[i], _b = k[j];              \
        bool _p = _a < _b;                                    \
        k[i] = _p ? _b : _a;                                  \
        k[j] = _p ? _a : _b;                                  \
    }

__global__ __launch_bounds__(128, 10)
void topk_router_kernel(const float* __restrict__ logits,
                        const float* __restrict__ bias,
                        float* __restrict__ out_w,
                        float* __restrict__ out_id,
                        int T)
{
    const int gwarp = (blockIdx.x * blockDim.x + threadIdx.x) >> 5;
    const int lane  = threadIdx.x & 31;
    const int q     = lane & 15;          // lane within my half
    const bool halfB = lane >= 16;

    const int t0 = gwarp * 2;
    if (t0 >= T) return;
    const bool pair = (t0 + 1 < T);
    const int  t1   = pair ? t0 + 1 : t0;

    const float* row = logits + (size_t)(halfB ? t1 : t0) * 256;

    // ---- each lane loads its 16 experts (4x LDG.128) + matching bias ----
    float s[16];
    {
        const float4 v0 = __ldg(reinterpret_cast<const float4*>(row + q * 16));
        const float4 v1 = __ldg(reinterpret_cast<const float4*>(row + q * 16 + 4));
        const float4 v2 = __ldg(reinterpret_cast<const float4*>(row + q * 16 + 8));
        const float4 v3 = __ldg(reinterpret_cast<const float4*>(row + q * 16 + 12));
        const float4 c0 = __ldg(reinterpret_cast<const float4*>(bias + q * 16));
        const float4 c1 = __ldg(reinterpret_cast<const float4*>(bias + q * 16 + 4));
        const float4 c2 = __ldg(reinterpret_cast<const float4*>(bias + q * 16 + 8));
        const float4 c3 = __ldg(reinterpret_cast<const float4*>(bias + q * 16 + 12));
        s[0]=v0.x+c0.x; s[1]=v0.y+c0.y; s[2]=v0.z+c0.z; s[3]=v0.w+c0.w;
        s[4]=v1.x+c1.x; s[5]=v1.y+c1.y; s[6]=v1.z+c1.z; s[7]=v1.w+c1.w;
        s[8]=v2.x+c2.x; s[9]=v2.y+c2.y; s[10]=v2.z+c2.z; s[11]=v2.w+c2.w;
        s[12]=v3.x+c3.x; s[13]=v3.y+c3.y; s[14]=v3.z+c3.z; s[15]=v3.w+c3.w;
    }

    // ---- per-lane top-2 of 16 (exact; ties irrelevant for a sum) ----
    float m1 = s[0], m2 = __int_as_float(0xff800000);
    #pragma unroll
    for (int e = 1; e < 16; e++) {
        float t = fminf(m1, s[e]);
        m1 = fmaxf(m1, s[e]);
        m2 = fmaxf(m2, t);
    }
    // merge with pair lane (group g = q>>1 spans lanes 2g, 2g+1 of my half);
    // 2nd-of-4 = max(both seconds, min of firsts): exact, predicate-free.
    {
        float o1 = __shfl_xor_sync(FULL, m1, 1);
        float o2 = __shfl_xor_sync(FULL, m2, 1);
        m2 = fmaxf(fmaxf(m2, o2), fminf(m1, o1));
        m1 = fmaxf(m1, o1);
    }
    const float gs = m1 + m2;             // group score, pair-replicated

    // ---- distributed rank among my half's 8 groups ----
    // lane q = 2g+b checks groups h = 4b..4b+3; pair-sum completes the rank.
    const int g = q >> 1;
    const int b = q & 1;
    const unsigned hbase = (lane & 16u) | ((unsigned)b << 3);  // shfl idx base
    int part = 0;
    #pragma unroll
    for (int i = 0; i < 4; i++) {
        const int h = (b << 2) | i;
        float gh = __shfl_sync(FULL, gs, hbase | (i << 1));
        part += (int)((gh > gs) || (gh == gs && h < g));
    }
    part += __shfl_xor_sync(FULL, part, 1);
    const unsigned bal = __ballot_sync(FULL, part < 4);   // both halves at once

    // ---- compaction within my half: pick my alive group ----
    const unsigned gb = (halfB ? (bal >> 16) : bal) & 0x5555u;  // bit 2g
    const int ai = q >> 2;                 // which alive group I take
    const unsigned x1 = gb & (gb - 1);
    const unsigned x2 = x1 & (x1 - 1);
    const unsigned x3 = x2 & (x2 - 1);
    unsigned pick = (ai == 0) ? gb : (ai == 1) ? x1 : (ai == 2) ? x2 : x3;
    const int m      = q & 3;
    const int src_q  = (__ffs(pick) - 1) + (m >> 1);      // 2g + (m>>1), 0..15
    const int src    = (lane & 16) + src_q;                // absolute lane
    const bool hi8   = (m & 1);                            // slots 8..15?

    // gather 8 scores from src (two sweeps: s[e] then s[8+e]); key =
    // (ord score << 32) | (255 - expert_id). u64 desc == (score desc, id asc);
    // compacted lane order is ascending expert id so lowest-lane-wins holds.
    unsigned long long k[8];
    const unsigned base = 255u - ((unsigned)src_q << 4) - (hi8 ? 8u : 0u);
    #pragma unroll
    for (int e = 0; e < 8; e++) {
        float p0v = __shfl_sync(FULL, s[e], src);
        float p1v = __shfl_sync(FULL, s[8 + e], src);
        float f   = hi8 ? p1v : p0v;
        k[e] = ((unsigned long long)f2ord(f) << 32)
             | (unsigned long long)(base - (unsigned)e);
    }

    // ---- Batcher odd-even mergesort of 8, descending, 19 CEs ----
    CE(0,1) CE(2,3) CE(4,5) CE(6,7)
    CE(0,2) CE(1,3) CE(4,6) CE(5,7)
    CE(1,2) CE(5,6)
    CE(0,4) CE(1,5) CE(2,6) CE(3,7)
    CE(2,4) CE(3,5)
    CE(1,2) CE(3,4) CE(5,6)

    // ---- 8 extraction rounds; 4-level butterfly within each 16-lane half ----
    const unsigned hm = halfB ? 0xFFFF0000u : 0x0000FFFFu;
    const unsigned sel[4] = {0x3214u, 0x3240u, 0x3410u, 0x4210u};
    unsigned p0 = 0, p1 = 0;
    #pragma unroll
    for (int it = 0; it < TOPK; it++) {
        unsigned hk = (unsigned)(k[0] >> 32);
        unsigned mx = hk;
        #pragma unroll
        for (int off = 1; off < 16; off <<= 1) {   // offsets 1,2,4,8: in-half
            unsigned o = __shfl_xor_sync(FULL, mx, off);
            mx = (o > mx) ? o : mx;
        }
        unsigned blt = __ballot_sync(FULL, hk == mx) & hm;
        int wl = __ffs(blt) - 1;                   // lowest lane = lowest id
        unsigned lo = __shfl_sync(FULL, (unsigned)k[0], wl);
        unsigned id = lo ^ 255u;                   // lo < 256: 255-(255-id)
        if (it < 4) p0 = __byte_perm(p0, id, sel[it]);
        else        p1 = __byte_perm(p1, id, sel[it - 4]);
        bool amw = (lane == wl);
        #pragma unroll
        for (int d = 0; d < 7 - it; d++)
            if (amw) k[d] = k[d + 1];
    }

    // ---- epilogue: lanes 0-7 emit token A, lanes 16-23 token B ----
    const unsigned pk   = (q < 4) ? p0 : p1;
    const unsigned myid = (pk >> ((lane & 3) * 8)) & 255u;

    float w = 0.0f;
    if (q < 8) w = __ldg(row + myid);          // exact unbiased logit, L1-hot
    float wsum = w;
    wsum += __shfl_xor_sync(FULL, wsum, 1);
    wsum += __shfl_xor_sync(FULL, wsum, 2);
    wsum += __shfl_xor_sync(FULL, wsum, 4);
    const float inv = __fdividef(SCALE, wsum);

    if ((q < 8) && (!halfB || pair)) {
        size_t o = (size_t)(halfB ? t1 : t0) * TOPK + q;
        out_w[o]  = w * inv;
        out_id[o] = (float)myid;
    }
}

extern "C" void kernel_launch(void* const* d_in, const int* in_sizes, int n_in,
                              void* d_out, int out_size)
{
    const float* logits = (const float*)d_in[0];
    const float* bias   = (const float*)d_in[1];
    const int T = in_sizes[0] / 256;

    float* out_w  = (float*)d_out;
    float* out_id = out_w + (size_t)T * TOPK;      // [weights | ids] halves

    const int threads = 128;                       // 4 warps x 2 tokens
    const int blocks  = (T + 7) / 8;
    topk_router_kernel<<<blocks, threads>>>(logits, bias, out_w, out_id, T);
}

// round 16
// speedup vs baseline: 1.2059x; 1.2059x over previous
#include <cuda_runtime.h>

// DeepSeek-V3 grouped top-k router, round 15.
// R11 champion skeleton (warp = 2 tokens, shuffle compaction, one u64
// sort/warp, butterfly+ballot extraction) with the shift-pop SELs replaced
// by a smem head-pointer queue (pops move to the LSU pipe) and the verified
// predicate-free top-2 merge. All tie-breaks bit-exact vs jax.lax.top_k.

#define FULL  0xFFFFFFFFu
#define TOPK  8
#define SCALE 2.5f

__device__ __forceinline__ unsigned f2ord(float f) {
    unsigned u = __float_as_uint(f);
    return u ^ (unsigned)(((int)u >> 31) | 0x80000000);   // monotonic f32->u32
}

// descending compare-exchange on u64 keys
#define CE(i, j)                                              \
    {                                                         \
        unsigned long long _a = k[i], _b = k[j];              \
        bool _p = _a < _b;                                    \
        k[i] = _p ? _b : _a;                                  \
        k[j] = _p ? _a : _b;                                  \
    }

__global__ __launch_bounds__(128, 14)
void topk_router_kernel(const float* __restrict__ logits,
                        const float* __restrict__ bias,
                        float* __restrict__ out_w,
                        float* __restrict__ out_id,
                        int T)
{
    // sorted key queues: [pos][tid], row stride 1024B -> 2-phase LDS.64,
    // no cross-lane sharing (each thread reads only column tid).
    // row 8 = padding for the head==7 prefetch (never consumed).
    __shared__ unsigned long long sk[9][128];

    const int tid   = threadIdx.x;
    const int gwarp = (blockIdx.x * blockDim.x + tid) >> 5;
    const int lane  = tid & 31;
    const int g     = lane >> 2;
    const int j     = lane & 3;

    const int t0 = gwarp * 2;
    if (t0 >= T) return;
    const bool pair = (t0 + 1 < T);
    const int  t1   = pair ? t0 + 1 : t0;

    const float* rowA = logits + (size_t)t0 * 256;
    const float* rowB = logits + (size_t)t1 * 256;

    // all LDG.128 up front; latency overlaps the scoring phase
    const float4 ba = __ldg(reinterpret_cast<const float4*>(bias + lane * 8));
    const float4 bb = __ldg(reinterpret_cast<const float4*>(bias + lane * 8 + 4));
    const float4 aA = __ldg(reinterpret_cast<const float4*>(rowA + lane * 8));
    const float4 bA = __ldg(reinterpret_cast<const float4*>(rowA + lane * 8 + 4));
    const float4 aB = __ldg(reinterpret_cast<const float4*>(rowB + lane * 8));
    const float4 bB = __ldg(reinterpret_cast<const float4*>(rowB + lane * 8 + 4));

    float sA[8] = {aA.x + ba.x, aA.y + ba.y, aA.z + ba.z, aA.w + ba.w,
                   bA.x + bb.x, bA.y + bb.y, bA.z + bb.z, bA.w + bb.w};
    float sB[8] = {aB.x + ba.x, aB.y + ba.y, aB.z + ba.z, aB.w + ba.w,
                   bB.x + bb.x, bB.y + bb.y, bB.z + bb.z, bB.w + bb.w};

    // ---- group scores (exact f32 top-2 sums; ties irrelevant for a sum) ----
    float m1A = sA[0], m2A = __int_as_float(0xff800000);
    float m1B = sB[0], m2B = __int_as_float(0xff800000);
    #pragma unroll
    for (int e = 1; e < 8; e++) {
        float tA = fminf(m1A, sA[e]); m1A = fmaxf(m1A, sA[e]); m2A = fmaxf(m2A, tA);
        float tB = fminf(m1B, sB[e]); m1B = fmaxf(m1B, sB[e]); m2B = fmaxf(m2B, tB);
    }
    // merge 4 lanes; 2nd-of-4 = max(both seconds, min of firsts) — exact,
    // predicate-free (loser's second is dominated by loser's first).
    #pragma unroll
    for (int off = 1; off < 4; off <<= 1) {
        float o1A = __shfl_xor_sync(FULL, m1A, off);
        float o2A = __shfl_xor_sync(FULL, m2A, off);
        float o1B = __shfl_xor_sync(FULL, m1B, off);
        float o2B = __shfl_xor_sync(FULL, m2B, off);
        m2A = fmaxf(fmaxf(m2A, o2A), fminf(m1A, o1A));
        m2B = fmaxf(fmaxf(m2B, o2B), fminf(m1B, o1B));
        m1A = fmaxf(m1A, o1A);
        m1B = fmaxf(m1B, o1B);
    }
    const float gsA = m1A + m2A;
    const float gsB = m1B + m2B;

    // distributed rank, packed A|B<<8: lane 4g+j checks groups j and j+4
    const float ghA0 = __shfl_sync(FULL, gsA, j << 2);
    const float ghA1 = __shfl_sync(FULL, gsA, (j + 4) << 2);
    const float ghB0 = __shfl_sync(FULL, gsB, j << 2);
    const float ghB1 = __shfl_sync(FULL, gsB, (j + 4) << 2);
    const bool c0 = j < g, c1 = (j + 4) < g;
    unsigned part = (unsigned)((ghA0 > gsA) || (ghA0 == gsA && c0))
                  + (unsigned)((ghA1 > gsA) || (ghA1 == gsA && c1))
                  + (((unsigned)((ghB0 > gsB) || (ghB0 == gsB && c0))
                    + (unsigned)((ghB1 > gsB) || (ghB1 == gsB && c1))) << 8);
    part += __shfl_xor_sync(FULL, part, 1);
    part += __shfl_xor_sync(FULL, part, 2);
    const unsigned balA = __ballot_sync(FULL, (part & 255u) < 4);
    const unsigned balB = __ballot_sync(FULL, (part >> 8) < 4);

    // ---- compaction: lanes 0-15 take token A's alive groups, 16-31 B's ----
    const bool halfB = lane >= 16;
    const unsigned bal = halfB ? balB : balA;
    const unsigned gb  = bal & 0x11111111u;        // one bit per alive group
    const int ai = (lane >> 2) & 3;                // which alive group I want
    const unsigned x1 = gb & (gb - 1);
    const unsigned x2 = x1 & (x1 - 1);
    const unsigned x3 = x2 & (x2 - 1);
    unsigned pick = (ai == 0) ? gb : (ai == 1) ? x1 : (ai == 2) ? x2 : x3;
    const int src = (__ffs(pick) - 1) + j;         // source lane (0..31)

    // gather biased scores; key = (ord score << 32) | (255 - expert_id)
    // u64 descending == (score desc, id asc): exact top_k tie order, and
    // compacted lane order is ascending expert id so lowest-lane-wins holds.
    unsigned long long k[8];
    const unsigned base = 255u - ((unsigned)src << 3);
    #pragma unroll
    for (int e = 0; e < 8; e++) {
        float fA = __shfl_sync(FULL, sA[e], src);
        float fB = __shfl_sync(FULL, sB[e], src);
        float f  = halfB ? fB : fA;
        k[e] = ((unsigned long long)f2ord(f) << 32)
             | (unsigned long long)(base - (unsigned)e);
    }

    // ---- Batcher odd-even mergesort of 8, descending, 19 CEs ----
    CE(0,1) CE(2,3) CE(4,5) CE(6,7)
    CE(0,2) CE(1,3) CE(4,6) CE(5,7)
    CE(1,2) CE(5,6)
    CE(0,4) CE(1,5) CE(2,6) CE(3,7)
    CE(2,4) CE(3,5)
    CE(1,2) CE(3,4) CE(5,6)

    // spill sorted queue to smem; head-pointer pops replace register shifts
    #pragma unroll
    for (int p = 0; p < 8; p++) sk[p][tid] = k[p];

    // ---- 8 extraction rounds; butterfly max + ballot; LSU-side pops ----
    const unsigned hm = halfB ? 0xFFFF0000u : 0x0000FFFFu;
    const unsigned sel[4] = {0x3214u, 0x3240u, 0x3410u, 0x4210u};
    unsigned p0 = 0, p1 = 0;
    unsigned head = 0;
    unsigned long long cur = k[0];
    #pragma unroll
    for (int it = 0; it < TOPK; it++) {
        // prefetch successor; overlaps the butterfly (row 8 = harmless pad)
        unsigned long long nxt = sk[head + 1][tid];

        unsigned hk = (unsigned)(cur >> 32);
        unsigned mx = hk;
        #pragma unroll
        for (int off = 1; off < 16; off <<= 1) {   // offsets 1,2,4,8: in-half
            unsigned o = __shfl_xor_sync(FULL, mx, off);
            mx = (o > mx) ? o : mx;
        }
        unsigned blt = __ballot_sync(FULL, hk == mx) & hm;
        int wl = __ffs(blt) - 1;                   // lowest lane = lowest id
        unsigned lo = __shfl_sync(FULL, (unsigned)cur, wl);
        unsigned id = lo ^ 255u;                   // lo < 256: 255-(255-id)
        if (it < 4) p0 = __byte_perm(p0, id, sel[it]);
        else        p1 = __byte_perm(p1, id, sel[it - 4]);

        const bool amw = (lane == wl);
        head += (unsigned)amw;                     // winner advances its head
        cur = amw ? nxt : cur;
    }

    // ---- epilogue: lanes 0-7 emit token A, lanes 16-23 token B ----
    const int q = lane & 15;
    const unsigned pk   = (q < 4) ? p0 : p1;
    const unsigned myid = (pk >> ((lane & 3) * 8)) & 255u;
    const float* row = halfB ? rowB : rowA;

    float w = 0.0f;
    if (q < 8) w = __ldg(row + myid);          // exact unbiased logit, L1-hot
    float wsum = w;
    wsum += __shfl_xor_sync(FULL, wsum, 1);
    wsum += __shfl_xor_sync(FULL, wsum, 2);
    wsum += __shfl_xor_sync(FULL, wsum, 4);
    const float inv = __fdividef(SCALE, wsum);

    if ((q < 8) && (!halfB || pair)) {
        size_t o = (size_t)(halfB ? t1 : t0) * TOPK + q;
        out_w[o]  = w * inv;
        out_id[o] = (float)myid;
    }
}

extern "C" void kernel_launch(void* const* d_in, const int* in_sizes, int n_in,
                              void* d_out, int out_size)
{
    const float* logits = (const float*)d_in[0];
    const float* bias   = (const float*)d_in[1];
    const int T = in_sizes[0] / 256;

    float* out_w  = (float*)d_out;
    float* out_id = out_w + (size_t)T * TOPK;      // [weights | ids] halves

    const int threads = 128;                       // 4 warps x 2 tokens
    const int blocks  = (T + 7) / 8;
    topk_router_kernel<<<blocks, threads>>>(logits, bias, out_w, out_id, T);
}